// round 1
// baseline (speedup 1.0000x reference)
#include <cuda_runtime.h>
#include <math.h>

#define BATCH  4
#define SEQ    1500
#define NSTATE 1024
#define NHEAD  16
#define HDIM   64
#define TOK    (BATCH*SEQ)   // 6000

// Scratch (allocation-free rule: __device__ globals)
__device__ float g_q[TOK*NSTATE];
__device__ float g_k[TOK*NSTATE];
__device__ float g_v[TOK*NSTATE];
__device__ float g_att[TOK*NSTATE];

// ---------------------------------------------------------------------------
// GEMM: C[M,N] = A[M,K] @ W[N,K]^T + bias   (both operands K-contiguous)
// 128x128 block tile, BK=16, 256 threads, 8x8 micro-tile split into
// two 4-wide segments (rows ty*4 / 64+ty*4, cols tx*4 / 64+tx*4) so all
// shared reads are contiguous float4.
// ---------------------------------------------------------------------------
__global__ __launch_bounds__(256) void sgemm_nt_bias(
    const float* __restrict__ A, const float* __restrict__ W,
    const float* __restrict__ bias, float* __restrict__ C,
    int M, int N, int K)
{
    __shared__ float As[16][128];
    __shared__ float Bs[16][128];

    const int t  = threadIdx.x;
    const int tx = t & 15;
    const int ty = t >> 4;
    const int m0 = blockIdx.y * 128;
    const int n0 = blockIdx.x * 128;
    const int lr = t >> 2;   // 0..63  (row within 64-row load pass)
    const int lc = t & 3;    // float4 slot within 16-wide k chunk

    float acc[8][8];
    #pragma unroll
    for (int i = 0; i < 8; i++)
        #pragma unroll
        for (int j = 0; j < 8; j++) acc[i][j] = 0.f;

    for (int k0 = 0; k0 < K; k0 += 16) {
        #pragma unroll
        for (int p = 0; p < 2; p++) {
            int row = lr + p*64;
            int gm  = m0 + row;
            float4 va = make_float4(0.f,0.f,0.f,0.f);
            if (gm < M) va = *(const float4*)(A + (size_t)gm*K + k0 + lc*4);
            As[lc*4+0][row] = va.x;
            As[lc*4+1][row] = va.y;
            As[lc*4+2][row] = va.z;
            As[lc*4+3][row] = va.w;

            int gn = n0 + row;
            float4 vb = make_float4(0.f,0.f,0.f,0.f);
            if (gn < N) vb = *(const float4*)(W + (size_t)gn*K + k0 + lc*4);
            Bs[lc*4+0][row] = vb.x;
            Bs[lc*4+1][row] = vb.y;
            Bs[lc*4+2][row] = vb.z;
            Bs[lc*4+3][row] = vb.w;
        }
        __syncthreads();

        #pragma unroll
        for (int kk = 0; kk < 16; kk++) {
            float a[8], b[8];
            *(float4*)(a)   = *(const float4*)&As[kk][ty*4];
            *(float4*)(a+4) = *(const float4*)&As[kk][64 + ty*4];
            *(float4*)(b)   = *(const float4*)&Bs[kk][tx*4];
            *(float4*)(b+4) = *(const float4*)&Bs[kk][64 + tx*4];
            #pragma unroll
            for (int i = 0; i < 8; i++)
                #pragma unroll
                for (int j = 0; j < 8; j++)
                    acc[i][j] += a[i] * b[j];
        }
        __syncthreads();
    }

    // bias (cols always valid: N multiple of 128)
    float bvv[8];
    #pragma unroll
    for (int j = 0; j < 8; j++) {
        int gn = n0 + ((j < 4) ? (tx*4 + j) : (64 + tx*4 + (j-4)));
        bvv[j] = bias ? bias[gn] : 0.f;
    }

    #pragma unroll
    for (int i = 0; i < 8; i++) {
        int gm = m0 + ((i < 4) ? (ty*4 + i) : (64 + ty*4 + (i-4)));
        if (gm >= M) continue;
        float4 o0, o1;
        o0.x = acc[i][0] + bvv[0]; o0.y = acc[i][1] + bvv[1];
        o0.z = acc[i][2] + bvv[2]; o0.w = acc[i][3] + bvv[3];
        o1.x = acc[i][4] + bvv[4]; o1.y = acc[i][5] + bvv[5];
        o1.z = acc[i][6] + bvv[6]; o1.w = acc[i][7] + bvv[7];
        *(float4*)(C + (size_t)gm*N + n0 + tx*4)      = o0;
        *(float4*)(C + (size_t)gm*N + n0 + 64 + tx*4) = o1;
    }
}

// ---------------------------------------------------------------------------
// Flash attention, fp32. One block = 64 q-rows of one (b,h).
// 256 threads as 16x16 grid, 4x4 micro-tiles. Online softmax in registers,
// row reductions via width-16 shuffles (a row's 16 owners are one warp half).
// Shared layouts XOR-swizzled: element (row,col) at row*64 + (col ^ 4*((row>>2)&7))
// -> transpose stores ~2-way instead of 16-way, reads stay float4-aligned.
// ---------------------------------------------------------------------------
__device__ __forceinline__ int swzi(int row, int col) {
    return (row << 6) + (col ^ ((((row) >> 2) & 7) << 2));
}

__global__ __launch_bounds__(256) void attn_kernel(
    const float* __restrict__ Qg, const float* __restrict__ Kg,
    const float* __restrict__ Vg, float* __restrict__ Og)
{
    extern __shared__ float sm[];
    float* Qs = sm;          // [64][64] swizzled, [d][m]
    float* Ks = sm + 4096;   // [64][64] swizzled, [d][j]
    float* Vs = sm + 8192;   // [64][64] row-major, [j][d]
    float* Pt = sm + 12288;  // [64][64] swizzled, [j][m]

    const int t  = threadIdx.x;
    const int tx = t & 15;
    const int ty = t >> 4;
    const int b  = blockIdx.z;
    const int h  = blockIdx.y;
    const int q0 = blockIdx.x * 64;

    // Load Q tile transposed+swizzled: Qs[d][m]
    {
        const int mr = t >> 4;   // 16 rows per pass
        const int d4 = t & 15;
        #pragma unroll
        for (int p = 0; p < 4; p++) {
            int m = mr + p*16;
            int s = q0 + m;
            float4 vq = make_float4(0.f,0.f,0.f,0.f);
            if (s < SEQ)
                vq = *(const float4*)(Qg + ((size_t)(b*SEQ + s)*NHEAD + h)*HDIM + d4*4);
            Qs[swzi(d4*4+0, m)] = vq.x;
            Qs[swzi(d4*4+1, m)] = vq.y;
            Qs[swzi(d4*4+2, m)] = vq.z;
            Qs[swzi(d4*4+3, m)] = vq.w;
        }
    }

    float o_acc[4][4];
    float m_run[4], l_run[4];
    #pragma unroll
    for (int i = 0; i < 4; i++) {
        m_run[i] = -INFINITY; l_run[i] = 0.f;
        #pragma unroll
        for (int j = 0; j < 4; j++) o_acc[i][j] = 0.f;
    }

    const int nkt = (SEQ + 63) / 64;
    for (int kt = 0; kt < nkt; kt++) {
        const int k0 = kt * 64;
        __syncthreads();   // protect Ks/Vs overwrite vs previous phase C

        // Load K (transposed+swizzled) and V (row-major) tiles
        {
            const int jr = t >> 4;
            const int d4 = t & 15;
            #pragma unroll
            for (int p = 0; p < 4; p++) {
                int j = jr + p*16;
                int s = k0 + j;
                float4 kv = make_float4(0.f,0.f,0.f,0.f);
                float4 vv = make_float4(0.f,0.f,0.f,0.f);
                if (s < SEQ) {
                    size_t base = ((size_t)(b*SEQ + s)*NHEAD + h)*HDIM + d4*4;
                    kv = *(const float4*)(Kg + base);
                    vv = *(const float4*)(Vg + base);
                }
                Ks[swzi(d4*4+0, j)] = kv.x;
                Ks[swzi(d4*4+1, j)] = kv.y;
                Ks[swzi(d4*4+2, j)] = kv.z;
                Ks[swzi(d4*4+3, j)] = kv.w;
                *(float4*)(Vs + j*64 + d4*4) = vv;
            }
        }
        __syncthreads();

        // Phase A: S = Q K^T (thread rows ty*4+mi, cols tx*4+ni)
        float sreg[4][4];
        #pragma unroll
        for (int mi = 0; mi < 4; mi++)
            #pragma unroll
            for (int ni = 0; ni < 4; ni++) sreg[mi][ni] = 0.f;

        #pragma unroll 8
        for (int d = 0; d < 64; d++) {
            float4 a4 = *(const float4*)(Qs + swzi(d, ty*4));
            float4 b4 = *(const float4*)(Ks + swzi(d, tx*4));
            float a[4] = {a4.x, a4.y, a4.z, a4.w};
            float bb[4] = {b4.x, b4.y, b4.z, b4.w};
            #pragma unroll
            for (int mi = 0; mi < 4; mi++)
                #pragma unroll
                for (int ni = 0; ni < 4; ni++)
                    sreg[mi][ni] += a[mi] * bb[ni];
        }

        // Phase B: mask, scale, online softmax (per-row, width-16 reductions)
        #pragma unroll
        for (int mi = 0; mi < 4; mi++) {
            float mx = -INFINITY;
            #pragma unroll
            for (int ni = 0; ni < 4; ni++) {
                int jg = k0 + tx*4 + ni;
                sreg[mi][ni] = (jg < SEQ) ? sreg[mi][ni] * 0.125f : -INFINITY;
                mx = fmaxf(mx, sreg[mi][ni]);
            }
            #pragma unroll
            for (int off = 8; off >= 1; off >>= 1)
                mx = fmaxf(mx, __shfl_xor_sync(0xffffffffu, mx, off, 16));
            float m_new = fmaxf(m_run[mi], mx);
            float alpha = __expf(m_run[mi] - m_new);
            float lsum = 0.f;
            #pragma unroll
            for (int ni = 0; ni < 4; ni++) {
                float p = __expf(sreg[mi][ni] - m_new);
                sreg[mi][ni] = p;
                lsum += p;
            }
            #pragma unroll
            for (int off = 8; off >= 1; off >>= 1)
                lsum += __shfl_xor_sync(0xffffffffu, lsum, off, 16);
            l_run[mi] = l_run[mi] * alpha + lsum;
            m_run[mi] = m_new;
            #pragma unroll
            for (int ni = 0; ni < 4; ni++) o_acc[mi][ni] *= alpha;
        }

        // Write P^T (swizzled [j][m])
        #pragma unroll
        for (int ni = 0; ni < 4; ni++)
            #pragma unroll
            for (int mi = 0; mi < 4; mi++)
                Pt[swzi(tx*4 + ni, ty*4 + mi)] = sreg[mi][ni];
        __syncthreads();

        // Phase C: O += P V (thread rows ty*4+mi, d-cols tx*4+ni)
        #pragma unroll 4
        for (int j = 0; j < 64; j++) {
            float4 a4 = *(const float4*)(Pt + swzi(j, ty*4));
            float4 b4 = *(const float4*)(Vs + j*64 + tx*4);
            float a[4] = {a4.x, a4.y, a4.z, a4.w};
            float bb[4] = {b4.x, b4.y, b4.z, b4.w};
            #pragma unroll
            for (int mi = 0; mi < 4; mi++)
                #pragma unroll
                for (int ni = 0; ni < 4; ni++)
                    o_acc[mi][ni] += a[mi] * bb[ni];
        }
    }

    // Epilogue: normalize and store [B,S,H,D]
    #pragma unroll
    for (int mi = 0; mi < 4; mi++) {
        int s = q0 + ty*4 + mi;
        if (s < SEQ) {
            float inv = 1.f / l_run[mi];
            float4 o;
            o.x = o_acc[mi][0] * inv;
            o.y = o_acc[mi][1] * inv;
            o.z = o_acc[mi][2] * inv;
            o.w = o_acc[mi][3] * inv;
            *(float4*)(Og + ((size_t)(b*SEQ + s)*NHEAD + h)*HDIM + tx*4) = o;
        }
    }
}

// ---------------------------------------------------------------------------
extern "C" void kernel_launch(void* const* d_in, const int* in_sizes, int n_in,
                              void* d_out, int out_size)
{
    const float* x  = (const float*)d_in[0];
    const float* Wq = (const float*)d_in[1];
    const float* bq = (const float*)d_in[2];
    const float* Wk = (const float*)d_in[3];
    const float* Wv = (const float*)d_in[4];
    const float* bv = (const float*)d_in[5];
    const float* Wo = (const float*)d_in[6];
    const float* bo = (const float*)d_in[7];
    float* out = (float*)d_out;

    float *q, *k, *v, *att;
    cudaGetSymbolAddress((void**)&q,   g_q);
    cudaGetSymbolAddress((void**)&k,   g_k);
    cudaGetSymbolAddress((void**)&v,   g_v);
    cudaGetSymbolAddress((void**)&att, g_att);

    const int attn_smem = 4 * 64 * 64 * (int)sizeof(float);  // 65536 B
    cudaFuncSetAttribute(attn_kernel,
                         cudaFuncAttributeMaxDynamicSharedMemorySize, attn_smem);

    dim3 gg(NSTATE/128, (TOK + 127)/128);   // (8, 47)
    sgemm_nt_bias<<<gg, 256>>>(x,   Wq, bq,      q,   TOK, NSTATE, NSTATE);
    sgemm_nt_bias<<<gg, 256>>>(x,   Wk, nullptr, k,   TOK, NSTATE, NSTATE);
    sgemm_nt_bias<<<gg, 256>>>(x,   Wv, bv,      v,   TOK, NSTATE, NSTATE);

    attn_kernel<<<dim3((SEQ+63)/64, NHEAD, BATCH), 256, attn_smem>>>(q, k, v, att);

    sgemm_nt_bias<<<gg, 256>>>(att, Wo, bo,      out, TOK, NSTATE, NSTATE);
}

// round 3
// speedup vs baseline: 3.7576x; 3.7576x over previous
#include <cuda_runtime.h>
#include <math.h>
#include <stdint.h>

#define BATCH  4
#define SEQ    1500
#define NSTATE 1024
#define NHEAD  16
#define HDIM   64
#define TOK    (BATCH*SEQ)   // 6000

// Scratch (allocation-free rule: __device__ globals)
__device__ float g_q[TOK*NSTATE];
__device__ float g_k[TOK*NSTATE];
__device__ float g_v[TOK*NSTATE];
__device__ float g_att[TOK*NSTATE];
__device__ float g_x[TOK*NSTATE];          // tf32-rounded x
__device__ float g_wq[NSTATE*NSTATE];
__device__ float g_wk[NSTATE*NSTATE];
__device__ float g_wv[NSTATE*NSTATE];
__device__ float g_wo[NSTATE*NSTATE];

// ===========================================================================
// helpers
// ===========================================================================
__device__ __forceinline__ uint32_t s2u(const void* p) {
    uint32_t a;
    asm("{ .reg .u64 t; cvta.to.shared.u64 t, %1; cvt.u32.u64 %0, t; }"
        : "=r"(a) : "l"(p));
    return a;
}

__device__ __forceinline__ float to_tf32(float x) {
    float r;
    asm("cvt.rna.tf32.f32 %0, %1;" : "=f"(r) : "f"(x));
    return r;
}

__device__ __forceinline__ void ldsm4(uint32_t& r0, uint32_t& r1,
                                      uint32_t& r2, uint32_t& r3, uint32_t addr) {
    asm volatile("ldmatrix.sync.aligned.m8n8.x4.shared.b16 {%0,%1,%2,%3}, [%4];"
        : "=r"(r0), "=r"(r1), "=r"(r2), "=r"(r3) : "r"(addr));
}

__device__ __forceinline__ void mma8(float* c, uint32_t a0, uint32_t a1,
                                     uint32_t a2, uint32_t a3,
                                     uint32_t b0, uint32_t b1) {
    asm volatile("mma.sync.aligned.m16n8k8.row.col.f32.tf32.tf32.f32 "
        "{%0,%1,%2,%3}, {%4,%5,%6,%7}, {%8,%9}, {%0,%1,%2,%3};"
        : "+f"(c[0]), "+f"(c[1]), "+f"(c[2]), "+f"(c[3])
        : "r"(a0), "r"(a1), "r"(a2), "r"(a3), "r"(b0), "r"(b1));
}

#define CP16(dst, src) \
    asm volatile("cp.async.cg.shared.global [%0], [%1], 16;" :: "r"(dst), "l"(src))
#define CP16P(dst, src, sz) \
    asm volatile("cp.async.cg.shared.global [%0], [%1], 16, %2;" :: "r"(dst), "l"(src), "r"(sz))
#define CP_COMMIT() asm volatile("cp.async.commit_group;" ::: "memory")
#define CP_WAIT(n)  asm volatile("cp.async.wait_group %0;" :: "n"(n) : "memory")

// ===========================================================================
// prepass: round fp32 -> tf32 bit pattern
// ===========================================================================
__global__ void round_tf32_kernel(const float* __restrict__ src,
                                  float* __restrict__ dst, int n) {
    int i = (blockIdx.x * blockDim.x + threadIdx.x) * 4;
    if (i < n) {
        float4 v = *(const float4*)(src + i);
        v.x = to_tf32(v.x); v.y = to_tf32(v.y);
        v.z = to_tf32(v.z); v.w = to_tf32(v.w);
        *(float4*)(dst + i) = v;
    }
}

// ===========================================================================
// GEMM: C[M,1024] = A[M,1024] @ W[1024,1024]^T + bias (tf32 mma.sync)
// Block 128x128, BK=32, 256 thr = 8 warps (2 m x 4 n), warp tile 64x32.
// SMEM rows padded to 144B (36 floats): LDSM conflict-free.
// ===========================================================================
#define G_STRIDE  36                    // floats per smem row
#define G_STAGE_F (256*G_STRIDE)        // A(128)+B(128) rows = 9216 floats
#define G_STAGE_B (G_STAGE_F*4)         // 36864 bytes
#define GEMM_SMEM (2*G_STAGE_B)         // 73728

template<bool ROUND>
__global__ __launch_bounds__(256, 2) void gemm_tc(
    const float* __restrict__ A, const float* __restrict__ W,
    const float* __restrict__ bias, float* __restrict__ C, int M)
{
    extern __shared__ __align__(16) float sm[];
    const uint32_t sb = s2u(sm);
    const int tid = threadIdx.x;
    const int wid = tid >> 5, lane = tid & 31;
    const int wm = wid >> 2, wn = wid & 3;
    const int g = lane >> 2, q = lane & 3;
    const int sub = lane >> 3, r = lane & 7;
    const int m0 = blockIdx.y * 128;
    const int n0 = blockIdx.x * 128;

    // per-lane ldmatrix bases (byte offsets within stage)
    uint32_t aBase[4], bBase[2];
    #pragma unroll
    for (int mi = 0; mi < 4; mi++)
        aBase[mi] = (uint32_t)((64*wm + 16*mi + r + (sub&1)*8) * 144 + (sub>>1)*16);
    #pragma unroll
    for (int p = 0; p < 2; p++)
        bBase[p] = (uint32_t)(128*144 + (32*wn + 16*p + r + (sub>>1)*8) * 144 + (sub&1)*16);

    float c[4][4][4];
    #pragma unroll
    for (int mi = 0; mi < 4; mi++)
        #pragma unroll
        for (int ni = 0; ni < 4; ni++)
            #pragma unroll
            for (int e = 0; e < 4; e++) c[mi][ni][e] = 0.f;

    // loader: 1024 A-chunks + 1024 B-chunks of 16B, 8 per thread
    auto load_stage = [&](int s) {
        const uint32_t base = sb + (s & 1) * G_STAGE_B;
        const int k0 = s * 32;
        #pragma unroll
        for (int i = 0; i < 4; i++) {
            int idx = tid + 256*i;
            int row = idx >> 3, lc = idx & 7;
            // A
            int gm = m0 + row;
            const float* asrc = A + (size_t)(gm < M ? gm : 0) * NSTATE + k0 + lc*4;
            CP16P(base + row*144 + lc*16, asrc, (gm < M) ? 16 : 0);
            // B
            const float* bsrc = W + (size_t)(n0 + row) * NSTATE + k0 + lc*4;
            CP16(base + 128*144 + row*144 + lc*16, bsrc);
        }
    };

    load_stage(0); CP_COMMIT();
    for (int s = 0; s < 32; s++) {
        if (s + 1 < 32) { load_stage(s + 1); CP_COMMIT(); }
        else            { CP_COMMIT(); }
        CP_WAIT(1);
        __syncthreads();

        const uint32_t stg = sb + (s & 1) * G_STAGE_B;
        #pragma unroll
        for (int kd = 0; kd < 4; kd++) {
            uint32_t a[4][4];
            #pragma unroll
            for (int mi = 0; mi < 4; mi++)
                ldsm4(a[mi][0], a[mi][1], a[mi][2], a[mi][3],
                      stg + aBase[mi] + kd*32);
            #pragma unroll
            for (int p = 0; p < 2; p++) {
                uint32_t b0, b1, b2, b3;
                ldsm4(b0, b1, b2, b3, stg + bBase[p] + kd*32);
                #pragma unroll
                for (int mi = 0; mi < 4; mi++) {
                    mma8(c[mi][2*p],   a[mi][0], a[mi][1], a[mi][2], a[mi][3], b0, b1);
                    mma8(c[mi][2*p+1], a[mi][0], a[mi][1], a[mi][2], a[mi][3], b2, b3);
                }
            }
        }
        __syncthreads();
    }

    // epilogue
    #pragma unroll
    for (int ni = 0; ni < 4; ni++) {
        const int col = n0 + 32*wn + 8*ni + 2*q;
        float bx = 0.f, by = 0.f;
        if (bias) { bx = bias[col]; by = bias[col+1]; }
        #pragma unroll
        for (int mi = 0; mi < 4; mi++) {
            int row_lo = m0 + 64*wm + 16*mi + g;
            float v0 = c[mi][ni][0] + bx, v1 = c[mi][ni][1] + by;
            float v2 = c[mi][ni][2] + bx, v3 = c[mi][ni][3] + by;
            if (ROUND) { v0 = to_tf32(v0); v1 = to_tf32(v1);
                         v2 = to_tf32(v2); v3 = to_tf32(v3); }
            if (row_lo < M)
                *(float2*)(C + (size_t)row_lo*NSTATE + col) = make_float2(v0, v1);
            if (row_lo + 8 < M)
                *(float2*)(C + (size_t)(row_lo+8)*NSTATE + col) = make_float2(v2, v3);
        }
    }
}

// ===========================================================================
// Flash attention with tf32 mma.sync. BQ=128, BKV=64, 256 thr = 8 warps.
// Warp w owns 16 q-rows, full 64 kv-cols. Softmax warp-local (quad shuffles).
// SMEM: Qs[128][68], Ks[64][68], Vs[64][72], Ps[128][68] (floats).
// ===========================================================================
#define Q0F  0
#define K0F  8704
#define V0F  13056
#define P0F  17664
#define ATT_SMEM ((P0F + 8704) * 4)     // 105472 bytes

__global__ __launch_bounds__(256, 2) void attn_tc(
    const float* __restrict__ Qg, const float* __restrict__ Kg,
    const float* __restrict__ Vg, float* __restrict__ Og)
{
    extern __shared__ __align__(16) float sm[];
    const uint32_t sb = s2u(sm);
    const int tid  = threadIdx.x;
    const int w    = tid >> 5, lane = tid & 31;
    const int g    = lane >> 2, q = lane & 3;
    const int sub  = lane >> 3, r = lane & 7;
    const int q0   = blockIdx.x * 128;
    const int h    = blockIdx.y;
    const int b    = blockIdx.z;

    const uint32_t Qb = sb + Q0F*4, Kb = sb + K0F*4, Pb = sb + P0F*4;

    // ldmatrix per-lane bases
    const uint32_t qA = Qb + (uint32_t)((16*w + r + (sub&1)*8) * 272 + (sub>>1)*16);
    const uint32_t pA = Pb + (uint32_t)((16*w + r + (sub&1)*8) * 272 + (sub>>1)*16);
    uint32_t kB[4];
    #pragma unroll
    for (int p = 0; p < 4; p++)
        kB[p] = Kb + (uint32_t)((16*p + r + (sub>>1)*8) * 272 + (sub&1)*16);

    // load Q tile (2048 chunks of 16B, 8 per thread)
    {
        #pragma unroll
        for (int i = 0; i < 8; i++) {
            int idx = tid + 256*i;
            int row = idx >> 4, lc = idx & 15;
            int s = q0 + row;
            const float* src = Qg + ((size_t)(b*SEQ + (s < SEQ ? s : 0)))*NSTATE
                               + h*HDIM + lc*4;
            CP16P(Qb + row*272 + lc*16, src, (s < SEQ) ? 16 : 0);
        }
        CP_COMMIT();
    }

    float o[8][4];
    #pragma unroll
    for (int nt = 0; nt < 8; nt++)
        #pragma unroll
        for (int e = 0; e < 4; e++) o[nt][e] = 0.f;
    float m_lo = -1e30f, m_hi = -1e30f, l_lo = 0.f, l_hi = 0.f;

    const int NKT = (SEQ + 63) / 64;   // 24
    for (int kt = 0; kt < NKT; kt++) {
        __syncthreads();   // prev iter reads of Ks/Vs done
        // load K,V tiles (4 chunks each per thread)
        #pragma unroll
        for (int i = 0; i < 4; i++) {
            int idx = tid + 256*i;
            int row = idx >> 4, lc = idx & 15;
            int s = kt*64 + row;
            size_t base = ((size_t)(b*SEQ + (s < SEQ ? s : 0)))*NSTATE + h*HDIM + lc*4;
            int ok = (s < SEQ) ? 16 : 0;
            CP16P(Kb + row*272 + lc*16, Kg + base, ok);
            CP16P(sb + V0F*4 + row*288 + lc*16, Vg + base, ok);
        }
        CP_COMMIT();
        CP_WAIT(0);
        __syncthreads();

        // ---- S = Q K^T ----
        float s[8][4];
        #pragma unroll
        for (int nt = 0; nt < 8; nt++)
            #pragma unroll
            for (int e = 0; e < 4; e++) s[nt][e] = 0.f;

        #pragma unroll
        for (int kd = 0; kd < 8; kd++) {
            uint32_t a0, a1, a2, a3;
            ldsm4(a0, a1, a2, a3, qA + kd*32);
            #pragma unroll
            for (int p = 0; p < 4; p++) {
                uint32_t b0, b1, b2, b3;
                ldsm4(b0, b1, b2, b3, kB[p] + kd*32);
                mma8(s[2*p],   a0, a1, a2, a3, b0, b1);
                mma8(s[2*p+1], a0, a1, a2, a3, b2, b3);
            }
        }

        // ---- online softmax (rows g and g+8, warp-local) ----
        const int jb = kt*64 + 2*q;
        float mxlo = -1e30f, mxhi = -1e30f;
        #pragma unroll
        for (int nt = 0; nt < 8; nt++) {
            const int j0 = jb + 8*nt;
            s[nt][0] = (j0     < SEQ) ? s[nt][0]*0.125f : -1e30f;
            s[nt][1] = (j0 + 1 < SEQ) ? s[nt][1]*0.125f : -1e30f;
            s[nt][2] = (j0     < SEQ) ? s[nt][2]*0.125f : -1e30f;
            s[nt][3] = (j0 + 1 < SEQ) ? s[nt][3]*0.125f : -1e30f;
            mxlo = fmaxf(mxlo, fmaxf(s[nt][0], s[nt][1]));
            mxhi = fmaxf(mxhi, fmaxf(s[nt][2], s[nt][3]));
        }
        mxlo = fmaxf(mxlo, __shfl_xor_sync(0xffffffffu, mxlo, 1));
        mxlo = fmaxf(mxlo, __shfl_xor_sync(0xffffffffu, mxlo, 2));
        mxhi = fmaxf(mxhi, __shfl_xor_sync(0xffffffffu, mxhi, 1));
        mxhi = fmaxf(mxhi, __shfl_xor_sync(0xffffffffu, mxhi, 2));

        const float mn_lo = fmaxf(m_lo, mxlo);
        const float mn_hi = fmaxf(m_hi, mxhi);
        const float al_lo = __expf(m_lo - mn_lo);
        const float al_hi = __expf(m_hi - mn_hi);
        float sl = 0.f, sh = 0.f;
        #pragma unroll
        for (int nt = 0; nt < 8; nt++) {
            s[nt][0] = __expf(s[nt][0] - mn_lo);
            s[nt][1] = __expf(s[nt][1] - mn_lo);
            s[nt][2] = __expf(s[nt][2] - mn_hi);
            s[nt][3] = __expf(s[nt][3] - mn_hi);
            sl += s[nt][0] + s[nt][1];
            sh += s[nt][2] + s[nt][3];
        }
        sl += __shfl_xor_sync(0xffffffffu, sl, 1);
        sl += __shfl_xor_sync(0xffffffffu, sl, 2);
        sh += __shfl_xor_sync(0xffffffffu, sh, 1);
        sh += __shfl_xor_sync(0xffffffffu, sh, 2);
        l_lo = l_lo * al_lo + sl;  m_lo = mn_lo;
        l_hi = l_hi * al_hi + sh;  m_hi = mn_hi;
        #pragma unroll
        for (int nt = 0; nt < 8; nt++) {
            o[nt][0] *= al_lo; o[nt][1] *= al_lo;
            o[nt][2] *= al_hi; o[nt][3] *= al_hi;
        }

        // store P (tf32-rounded) to Ps
        {
            float* Prow_lo = sm + P0F + (16*w + g)     * 68 + 2*q;
            float* Prow_hi = sm + P0F + (16*w + g + 8) * 68 + 2*q;
            #pragma unroll
            for (int nt = 0; nt < 8; nt++) {
                *(float2*)(Prow_lo + 8*nt) = make_float2(to_tf32(s[nt][0]), to_tf32(s[nt][1]));
                *(float2*)(Prow_hi + 8*nt) = make_float2(to_tf32(s[nt][2]), to_tf32(s[nt][3]));
            }
        }
        __syncwarp();

        // ---- O += P V ----
        #pragma unroll
        for (int kj = 0; kj < 8; kj++) {
            uint32_t a0, a1, a2, a3;
            ldsm4(a0, a1, a2, a3, pA + kj*32);
            const float* vlo = sm + V0F + (8*kj + q)     * 72 + g;
            const float* vhi = sm + V0F + (8*kj + q + 4) * 72 + g;
            #pragma unroll
            for (int nt = 0; nt < 8; nt++) {
                uint32_t b0 = __float_as_uint(vlo[8*nt]);
                uint32_t b1 = __float_as_uint(vhi[8*nt]);
                mma8(o[nt], a0, a1, a2, a3, b0, b1);
            }
        }
        __syncwarp();
    }

    // ---- epilogue: normalize, round for Wo GEMM, store [tok][h*64+d] ----
    const float il_lo = 1.f / l_lo, il_hi = 1.f / l_hi;
    const int row_lo = q0 + 16*w + g;
    const int row_hi = row_lo + 8;
    #pragma unroll
    for (int nt = 0; nt < 8; nt++) {
        const int d = 8*nt + 2*q;
        if (row_lo < SEQ) {
            float2 v = make_float2(to_tf32(o[nt][0]*il_lo), to_tf32(o[nt][1]*il_lo));
            *(float2*)(Og + ((size_t)(b*SEQ + row_lo))*NSTATE + h*HDIM + d) = v;
        }
        if (row_hi < SEQ) {
            float2 v = make_float2(to_tf32(o[nt][2]*il_hi), to_tf32(o[nt][3]*il_hi));
            *(float2*)(Og + ((size_t)(b*SEQ + row_hi))*NSTATE + h*HDIM + d) = v;
        }
    }
}

// ===========================================================================
extern "C" void kernel_launch(void* const* d_in, const int* in_sizes, int n_in,
                              void* d_out, int out_size)
{
    const float* x  = (const float*)d_in[0];
    const float* Wq = (const float*)d_in[1];
    const float* bq = (const float*)d_in[2];
    const float* Wk = (const float*)d_in[3];
    const float* Wv = (const float*)d_in[4];
    const float* bv = (const float*)d_in[5];
    const float* Wo = (const float*)d_in[6];
    const float* bo = (const float*)d_in[7];
    float* out = (float*)d_out;

    float *q, *k, *v, *att, *xr, *wq, *wk, *wv, *wo;
    cudaGetSymbolAddress((void**)&q,   g_q);
    cudaGetSymbolAddress((void**)&k,   g_k);
    cudaGetSymbolAddress((void**)&v,   g_v);
    cudaGetSymbolAddress((void**)&att, g_att);
    cudaGetSymbolAddress((void**)&xr,  g_x);
    cudaGetSymbolAddress((void**)&wq,  g_wq);
    cudaGetSymbolAddress((void**)&wk,  g_wk);
    cudaGetSymbolAddress((void**)&wv,  g_wv);
    cudaGetSymbolAddress((void**)&wo,  g_wo);

    cudaFuncSetAttribute(gemm_tc<true>,
                         cudaFuncAttributeMaxDynamicSharedMemorySize, GEMM_SMEM);
    cudaFuncSetAttribute(gemm_tc<false>,
                         cudaFuncAttributeMaxDynamicSharedMemorySize, GEMM_SMEM);
    cudaFuncSetAttribute(attn_tc,
                         cudaFuncAttributeMaxDynamicSharedMemorySize, ATT_SMEM);

    // prepass: tf32-round x and weights
    const int nx = TOK * NSTATE, nw = NSTATE * NSTATE;
    round_tf32_kernel<<<nx/1024, 256>>>(x,  xr, nx);
    round_tf32_kernel<<<nw/1024, 256>>>(Wq, wq, nw);
    round_tf32_kernel<<<nw/1024, 256>>>(Wk, wk, nw);
    round_tf32_kernel<<<nw/1024, 256>>>(Wv, wv, nw);
    round_tf32_kernel<<<nw/1024, 256>>>(Wo, wo, nw);

    dim3 gg(NSTATE/128, (TOK + 127)/128);   // (8, 47)
    gemm_tc<true><<<gg, 256, GEMM_SMEM>>>(xr, wq, bq,      q, TOK);
    gemm_tc<true><<<gg, 256, GEMM_SMEM>>>(xr, wk, nullptr, k, TOK);
    gemm_tc<true><<<gg, 256, GEMM_SMEM>>>(xr, wv, bv,      v, TOK);

    attn_tc<<<dim3((SEQ+127)/128, NHEAD, BATCH), 256, ATT_SMEM>>>(q, k, v, att);

    gemm_tc<false><<<gg, 256, GEMM_SMEM>>>(att, wo, bo, out, TOK);
}

// round 4
// speedup vs baseline: 6.2812x; 1.6716x over previous
#include <cuda_runtime.h>
#include <cuda_fp16.h>
#include <math.h>
#include <stdint.h>

#define BATCH  4
#define SEQ    1500
#define NSTATE 1024
#define NHEAD  16
#define HDIM   64
#define TOK    (BATCH*SEQ)   // 6000

// Scratch (allocation-free rule: __device__ globals), all fp16
__device__ __half g_x[TOK*NSTATE];
__device__ __half g_q[TOK*NSTATE];
__device__ __half g_k[TOK*NSTATE];
__device__ __half g_v[TOK*NSTATE];
__device__ __half g_att[TOK*NSTATE];
__device__ __half g_wq[NSTATE*NSTATE];
__device__ __half g_wk[NSTATE*NSTATE];
__device__ __half g_wv[NSTATE*NSTATE];
__device__ __half g_wo[NSTATE*NSTATE];

// ===========================================================================
// helpers
// ===========================================================================
__device__ __forceinline__ uint32_t s2u(const void* p) {
    uint32_t a;
    asm("{ .reg .u64 t; cvta.to.shared.u64 t, %1; cvt.u32.u64 %0, t; }"
        : "=r"(a) : "l"(p));
    return a;
}

__device__ __forceinline__ void ldsm4(uint32_t& r0, uint32_t& r1,
                                      uint32_t& r2, uint32_t& r3, uint32_t addr) {
    asm volatile("ldmatrix.sync.aligned.m8n8.x4.shared.b16 {%0,%1,%2,%3}, [%4];"
        : "=r"(r0), "=r"(r1), "=r"(r2), "=r"(r3) : "r"(addr));
}
__device__ __forceinline__ void ldsm4t(uint32_t& r0, uint32_t& r1,
                                       uint32_t& r2, uint32_t& r3, uint32_t addr) {
    asm volatile("ldmatrix.sync.aligned.m8n8.x4.trans.shared.b16 {%0,%1,%2,%3}, [%4];"
        : "=r"(r0), "=r"(r1), "=r"(r2), "=r"(r3) : "r"(addr));
}

// fp16 m16n8k16, fp32 accumulate
__device__ __forceinline__ void mma16(float* c, uint32_t a0, uint32_t a1,
                                      uint32_t a2, uint32_t a3,
                                      uint32_t b0, uint32_t b1) {
    asm volatile("mma.sync.aligned.m16n8k16.row.col.f32.f16.f16.f32 "
        "{%0,%1,%2,%3}, {%4,%5,%6,%7}, {%8,%9}, {%0,%1,%2,%3};"
        : "+f"(c[0]), "+f"(c[1]), "+f"(c[2]), "+f"(c[3])
        : "r"(a0), "r"(a1), "r"(a2), "r"(a3), "r"(b0), "r"(b1));
}

#define CP16(dst, src) \
    asm volatile("cp.async.cg.shared.global [%0], [%1], 16;" :: "r"(dst), "l"(src))
#define CP16P(dst, src, sz) \
    asm volatile("cp.async.cg.shared.global [%0], [%1], 16, %2;" :: "r"(dst), "l"(src), "r"(sz))
#define CP_COMMIT() asm volatile("cp.async.commit_group;" ::: "memory")
#define CP_WAIT(n)  asm volatile("cp.async.wait_group %0;" :: "n"(n) : "memory")

// ===========================================================================
// prepass: fp32 -> fp16 (RN)
// ===========================================================================
__global__ void f2h_kernel(const float* __restrict__ src,
                           __half* __restrict__ dst, int n) {
    int i = (blockIdx.x * blockDim.x + threadIdx.x) * 8;
    if (i < n) {
        float4 v0 = *(const float4*)(src + i);
        float4 v1 = *(const float4*)(src + i + 4);
        __half2 h[4];
        h[0] = __floats2half2_rn(v0.x, v0.y);
        h[1] = __floats2half2_rn(v0.z, v0.w);
        h[2] = __floats2half2_rn(v1.x, v1.y);
        h[3] = __floats2half2_rn(v1.z, v1.w);
        *(uint4*)(dst + i) = *(uint4*)h;
    }
}

// ===========================================================================
// GEMM: C[M,1024] = A[M,1024] @ W[1024,1024]^T + bias (fp16 mma.sync)
// Block 128x128, BK=64 halves (128B rows), 256 thr = 8 warps (2m x 4n),
// warp tile 64x32. SMEM rows 144B: LDSM conflict-free. 16 K-stages.
// ===========================================================================
#define G_STAGE_B (256*144)             // 36864 bytes (A128 + B128 rows)
#define GEMM_SMEM (2*G_STAGE_B)         // 73728

template<bool HALF_OUT>
__global__ __launch_bounds__(256, 2) void gemm_tc(
    const __half* __restrict__ A, const __half* __restrict__ W,
    const float* __restrict__ bias, void* __restrict__ Cv, int M)
{
    extern __shared__ __align__(16) char smraw[];
    const uint32_t sb = s2u(smraw);
    const int tid = threadIdx.x;
    const int wid = tid >> 5, lane = tid & 31;
    const int wm = wid >> 2, wn = wid & 3;
    const int g = lane >> 2, q = lane & 3;
    const int m0 = blockIdx.y * 128;
    const int n0 = blockIdx.x * 128;

    const uint32_t lmRow = (uint32_t)(lane & 15) * 144 + (uint32_t)(lane >> 4) * 16;
    uint32_t aBase[4], bBase[2];
    #pragma unroll
    for (int mi = 0; mi < 4; mi++)
        aBase[mi] = (uint32_t)(64*wm + 16*mi) * 144 + lmRow;
    #pragma unroll
    for (int p = 0; p < 2; p++)
        bBase[p] = 128u*144 + (uint32_t)(32*wn + 16*p) * 144 + lmRow;

    float c[4][4][4];
    #pragma unroll
    for (int mi = 0; mi < 4; mi++)
        #pragma unroll
        for (int ni = 0; ni < 4; ni++)
            #pragma unroll
            for (int e = 0; e < 4; e++) c[mi][ni][e] = 0.f;

    auto load_stage = [&](int s) {
        const uint32_t base = sb + (s & 1) * G_STAGE_B;
        const int k0 = s * 64;
        #pragma unroll
        for (int i = 0; i < 4; i++) {
            int idx = tid + 256*i;
            int row = idx >> 3, lc = idx & 7;
            int gm = m0 + row;
            const __half* asrc = A + (size_t)(gm < M ? gm : 0) * NSTATE + k0 + lc*8;
            CP16P(base + row*144 + lc*16, asrc, (gm < M) ? 16 : 0);
            const __half* bsrc = W + (size_t)(n0 + row) * NSTATE + k0 + lc*8;
            CP16(base + 128*144 + row*144 + lc*16, bsrc);
        }
    };

    load_stage(0); CP_COMMIT();
    for (int s = 0; s < 16; s++) {
        if (s + 1 < 16) { load_stage(s + 1); CP_COMMIT(); }
        else            { CP_COMMIT(); }
        CP_WAIT(1);
        __syncthreads();

        const uint32_t stg = sb + (s & 1) * G_STAGE_B;
        #pragma unroll
        for (int kd = 0; kd < 4; kd++) {
            uint32_t a[4][4];
            #pragma unroll
            for (int mi = 0; mi < 4; mi++)
                ldsm4(a[mi][0], a[mi][1], a[mi][2], a[mi][3],
                      stg + aBase[mi] + kd*32);
            #pragma unroll
            for (int p = 0; p < 2; p++) {
                uint32_t t0, t1, t2, t3;
                ldsm4(t0, t1, t2, t3, stg + bBase[p] + kd*32);
                #pragma unroll
                for (int mi = 0; mi < 4; mi++) {
                    mma16(c[mi][2*p],   a[mi][0], a[mi][1], a[mi][2], a[mi][3], t0, t2);
                    mma16(c[mi][2*p+1], a[mi][0], a[mi][1], a[mi][2], a[mi][3], t1, t3);
                }
            }
        }
        __syncthreads();
    }

    // epilogue
    #pragma unroll
    for (int ni = 0; ni < 4; ni++) {
        const int col = n0 + 32*wn + 8*ni + 2*q;
        float bx = 0.f, by = 0.f;
        if (bias) { bx = bias[col]; by = bias[col+1]; }
        #pragma unroll
        for (int mi = 0; mi < 4; mi++) {
            int row_lo = m0 + 64*wm + 16*mi + g;
            float v0 = c[mi][ni][0] + bx, v1 = c[mi][ni][1] + by;
            float v2 = c[mi][ni][2] + bx, v3 = c[mi][ni][3] + by;
            if (HALF_OUT) {
                __half* C = (__half*)Cv;
                if (row_lo < M)
                    *(__half2*)(C + (size_t)row_lo*NSTATE + col) = __floats2half2_rn(v0, v1);
                if (row_lo + 8 < M)
                    *(__half2*)(C + (size_t)(row_lo+8)*NSTATE + col) = __floats2half2_rn(v2, v3);
            } else {
                float* C = (float*)Cv;
                if (row_lo < M)
                    *(float2*)(C + (size_t)row_lo*NSTATE + col) = make_float2(v0, v1);
                if (row_lo + 8 < M)
                    *(float2*)(C + (size_t)(row_lo+8)*NSTATE + col) = make_float2(v2, v3);
            }
        }
    }
}

// ===========================================================================
// Flash attention, fp16 mma.sync. BQ=128, BKV=64, 256 thr = 8 warps.
// Warp w: 16 q-rows x 64 kv-cols. Softmax warp-local (quad shuffles).
// SMEM (halves, rows 72h=144B): Q[128], K[64], V[64], P[128].
// V's B-fragments come from ldmatrix.x4.trans.b16 (row-major V).
// ===========================================================================
#define Q0H  0
#define K0H  9216
#define V0H  13824
#define P0H  18432
#define ATT_SMEM ((P0H + 9216) * 2)     // 55296 bytes

__global__ __launch_bounds__(256, 2) void attn_tc(
    const __half* __restrict__ Qg, const __half* __restrict__ Kg,
    const __half* __restrict__ Vg, __half* __restrict__ Og)
{
    extern __shared__ __align__(16) char smraw[];
    __half* smh = (__half*)smraw;
    const uint32_t sb = s2u(smraw);
    const int tid  = threadIdx.x;
    const int w    = tid >> 5, lane = tid & 31;
    const int g    = lane >> 2, q = lane & 3;
    const int q0   = blockIdx.x * 128;
    const int h    = blockIdx.y;
    const int b    = blockIdx.z;

    const uint32_t Qb = sb + Q0H*2, Kb = sb + K0H*2, Vb = sb + V0H*2, Pb = sb + P0H*2;
    const uint32_t lmRow = (uint32_t)(lane & 15) * 144 + (uint32_t)(lane >> 4) * 16;

    const uint32_t qA = Qb + (uint32_t)(16*w)*144 + lmRow;
    const uint32_t pA = Pb + (uint32_t)(16*w)*144 + lmRow;
    uint32_t kB[4];
    #pragma unroll
    for (int p = 0; p < 4; p++)
        kB[p] = Kb + (uint32_t)(16*p)*144 + lmRow;

    // load Q tile: 128 rows x 8 chunks = 1024, 4/thread
    {
        #pragma unroll
        for (int i = 0; i < 4; i++) {
            int idx = tid + 256*i;
            int row = idx >> 3, lc = idx & 7;
            int s = q0 + row;
            const __half* src = Qg + ((size_t)(b*SEQ + (s < SEQ ? s : 0)))*NSTATE
                                + h*HDIM + lc*8;
            CP16P(Qb + row*144 + lc*16, src, (s < SEQ) ? 16 : 0);
        }
        CP_COMMIT();
    }

    float o[8][4];
    #pragma unroll
    for (int nt = 0; nt < 8; nt++)
        #pragma unroll
        for (int e = 0; e < 4; e++) o[nt][e] = 0.f;
    float m_lo = -1e30f, m_hi = -1e30f, l_lo = 0.f, l_hi = 0.f;

    const int NKT = (SEQ + 63) / 64;   // 24
    for (int kt = 0; kt < NKT; kt++) {
        __syncthreads();
        // load K,V tiles: 64 rows x 8 chunks x 2 = 1024, 4/thread
        #pragma unroll
        for (int i = 0; i < 2; i++) {
            int idx = tid + 256*i;
            int row = idx >> 3, lc = idx & 7;
            int s = kt*64 + row;
            size_t base = ((size_t)(b*SEQ + (s < SEQ ? s : 0)))*NSTATE + h*HDIM + lc*8;
            int ok = (s < SEQ) ? 16 : 0;
            CP16P(Kb + row*144 + lc*16, Kg + base, ok);
            CP16P(Vb + row*144 + lc*16, Vg + base, ok);
        }
        CP_COMMIT();
        CP_WAIT(0);
        __syncthreads();

        // ---- S = Q K^T ----
        float s[8][4];
        #pragma unroll
        for (int nt = 0; nt < 8; nt++)
            #pragma unroll
            for (int e = 0; e < 4; e++) s[nt][e] = 0.f;

        #pragma unroll
        for (int kd = 0; kd < 4; kd++) {
            uint32_t a0, a1, a2, a3;
            ldsm4(a0, a1, a2, a3, qA + kd*32);
            #pragma unroll
            for (int p = 0; p < 4; p++) {
                uint32_t t0, t1, t2, t3;
                ldsm4(t0, t1, t2, t3, kB[p] + kd*32);
                mma16(s[2*p],   a0, a1, a2, a3, t0, t2);
                mma16(s[2*p+1], a0, a1, a2, a3, t1, t3);
            }
        }

        // ---- online softmax (rows g, g+8; warp-local) ----
        const int jb = kt*64 + 2*q;
        float mxlo = -1e30f, mxhi = -1e30f;
        #pragma unroll
        for (int nt = 0; nt < 8; nt++) {
            const int j0 = jb + 8*nt;
            s[nt][0] = (j0     < SEQ) ? s[nt][0]*0.125f : -1e30f;
            s[nt][1] = (j0 + 1 < SEQ) ? s[nt][1]*0.125f : -1e30f;
            s[nt][2] = (j0     < SEQ) ? s[nt][2]*0.125f : -1e30f;
            s[nt][3] = (j0 + 1 < SEQ) ? s[nt][3]*0.125f : -1e30f;
            mxlo = fmaxf(mxlo, fmaxf(s[nt][0], s[nt][1]));
            mxhi = fmaxf(mxhi, fmaxf(s[nt][2], s[nt][3]));
        }
        mxlo = fmaxf(mxlo, __shfl_xor_sync(0xffffffffu, mxlo, 1));
        mxlo = fmaxf(mxlo, __shfl_xor_sync(0xffffffffu, mxlo, 2));
        mxhi = fmaxf(mxhi, __shfl_xor_sync(0xffffffffu, mxhi, 1));
        mxhi = fmaxf(mxhi, __shfl_xor_sync(0xffffffffu, mxhi, 2));

        const float mn_lo = fmaxf(m_lo, mxlo);
        const float mn_hi = fmaxf(m_hi, mxhi);
        const float al_lo = __expf(m_lo - mn_lo);
        const float al_hi = __expf(m_hi - mn_hi);
        float sl = 0.f, sh = 0.f;
        #pragma unroll
        for (int nt = 0; nt < 8; nt++) {
            s[nt][0] = __expf(s[nt][0] - mn_lo);
            s[nt][1] = __expf(s[nt][1] - mn_lo);
            s[nt][2] = __expf(s[nt][2] - mn_hi);
            s[nt][3] = __expf(s[nt][3] - mn_hi);
            sl += s[nt][0] + s[nt][1];
            sh += s[nt][2] + s[nt][3];
        }
        sl += __shfl_xor_sync(0xffffffffu, sl, 1);
        sl += __shfl_xor_sync(0xffffffffu, sl, 2);
        sh += __shfl_xor_sync(0xffffffffu, sh, 1);
        sh += __shfl_xor_sync(0xffffffffu, sh, 2);
        l_lo = l_lo * al_lo + sl;  m_lo = mn_lo;
        l_hi = l_hi * al_hi + sh;  m_hi = mn_hi;
        #pragma unroll
        for (int nt = 0; nt < 8; nt++) {
            o[nt][0] *= al_lo; o[nt][1] *= al_lo;
            o[nt][2] *= al_hi; o[nt][3] *= al_hi;
        }

        // store P (fp16) rows 16w+g, 16w+g+8
        {
            __half* Plo = smh + P0H + (16*w + g)     * 72 + 2*q;
            __half* Phi = smh + P0H + (16*w + g + 8) * 72 + 2*q;
            #pragma unroll
            for (int nt = 0; nt < 8; nt++) {
                *(__half2*)(Plo + 8*nt) = __floats2half2_rn(s[nt][0], s[nt][1]);
                *(__half2*)(Phi + 8*nt) = __floats2half2_rn(s[nt][2], s[nt][3]);
            }
        }
        __syncwarp();

        // ---- O += P V (B via trans ldmatrix on row-major V) ----
        #pragma unroll
        for (int kj = 0; kj < 4; kj++) {
            uint32_t a0, a1, a2, a3;
            ldsm4(a0, a1, a2, a3, pA + kj*32);
            const uint32_t vrow = Vb + (uint32_t)(16*kj)*144 + lmRow;
            #pragma unroll
            for (int dt = 0; dt < 4; dt++) {
                uint32_t t0, t1, t2, t3;
                ldsm4t(t0, t1, t2, t3, vrow + dt*32);
                mma16(o[2*dt],   a0, a1, a2, a3, t0, t1);
                mma16(o[2*dt+1], a0, a1, a2, a3, t2, t3);
            }
        }
        __syncwarp();
    }

    // ---- epilogue: normalize, store fp16 att [tok][h*64+d] ----
    const float il_lo = 1.f / l_lo, il_hi = 1.f / l_hi;
    const int row_lo = q0 + 16*w + g;
    const int row_hi = row_lo + 8;
    #pragma unroll
    for (int nt = 0; nt < 8; nt++) {
        const int d = 8*nt + 2*q;
        if (row_lo < SEQ)
            *(__half2*)(Og + ((size_t)(b*SEQ + row_lo))*NSTATE + h*HDIM + d) =
                __floats2half2_rn(o[nt][0]*il_lo, o[nt][1]*il_lo);
        if (row_hi < SEQ)
            *(__half2*)(Og + ((size_t)(b*SEQ + row_hi))*NSTATE + h*HDIM + d) =
                __floats2half2_rn(o[nt][2]*il_hi, o[nt][3]*il_hi);
    }
}

// ===========================================================================
extern "C" void kernel_launch(void* const* d_in, const int* in_sizes, int n_in,
                              void* d_out, int out_size)
{
    const float* x  = (const float*)d_in[0];
    const float* Wq = (const float*)d_in[1];
    const float* bq = (const float*)d_in[2];
    const float* Wk = (const float*)d_in[3];
    const float* Wv = (const float*)d_in[4];
    const float* bv = (const float*)d_in[5];
    const float* Wo = (const float*)d_in[6];
    const float* bo = (const float*)d_in[7];
    float* out = (float*)d_out;

    __half *xh, *wq, *wk, *wv, *wo, *q, *k, *v, *att;
    cudaGetSymbolAddress((void**)&xh,  g_x);
    cudaGetSymbolAddress((void**)&wq,  g_wq);
    cudaGetSymbolAddress((void**)&wk,  g_wk);
    cudaGetSymbolAddress((void**)&wv,  g_wv);
    cudaGetSymbolAddress((void**)&wo,  g_wo);
    cudaGetSymbolAddress((void**)&q,   g_q);
    cudaGetSymbolAddress((void**)&k,   g_k);
    cudaGetSymbolAddress((void**)&v,   g_v);
    cudaGetSymbolAddress((void**)&att, g_att);

    cudaFuncSetAttribute(gemm_tc<true>,
                         cudaFuncAttributeMaxDynamicSharedMemorySize, GEMM_SMEM);
    cudaFuncSetAttribute(gemm_tc<false>,
                         cudaFuncAttributeMaxDynamicSharedMemorySize, GEMM_SMEM);
    cudaFuncSetAttribute(attn_tc,
                         cudaFuncAttributeMaxDynamicSharedMemorySize, ATT_SMEM);

    const int nx = TOK * NSTATE, nw = NSTATE * NSTATE;
    f2h_kernel<<<nx/2048, 256>>>(x,  xh, nx);
    f2h_kernel<<<nw/2048, 256>>>(Wq, wq, nw);
    f2h_kernel<<<nw/2048, 256>>>(Wk, wk, nw);
    f2h_kernel<<<nw/2048, 256>>>(Wv, wv, nw);
    f2h_kernel<<<nw/2048, 256>>>(Wo, wo, nw);

    dim3 gg(NSTATE/128, (TOK + 127)/128);   // (8, 47)
    gemm_tc<true><<<gg, 256, GEMM_SMEM>>>(xh, wq, bq,      q, TOK);
    gemm_tc<true><<<gg, 256, GEMM_SMEM>>>(xh, wk, nullptr, k, TOK);
    gemm_tc<true><<<gg, 256, GEMM_SMEM>>>(xh, wv, bv,      v, TOK);

    attn_tc<<<dim3((SEQ+127)/128, NHEAD, BATCH), 256, ATT_SMEM>>>(q, k, v, att);

    gemm_tc<false><<<gg, 256, GEMM_SMEM>>>(att, wo, bo, out, TOK);
}

// round 5
// speedup vs baseline: 6.7316x; 1.0717x over previous
#include <cuda_runtime.h>
#include <cuda_fp16.h>
#include <math.h>
#include <stdint.h>

#define BATCH  4
#define SEQ    1500
#define NSTATE 1024
#define NQKV   3072
#define NHEAD  16
#define HDIM   64
#define TOK    (BATCH*SEQ)   // 6000

// Scratch (allocation-free rule: __device__ globals), all fp16
__device__ __half g_x[TOK*NSTATE];
__device__ __half g_qkv[TOK*NQKV];          // fused q|k|v, row stride 3072
__device__ __half g_att[TOK*NSTATE];
__device__ __half g_wqkv[NQKV*NSTATE];      // Wq rows 0..1023, Wk 1024.., Wv 2048..
__device__ __half g_wo[NSTATE*NSTATE];
__device__ float  g_bqkv[NQKV];

// ===========================================================================
// helpers
// ===========================================================================
__device__ __forceinline__ uint32_t s2u(const void* p) {
    uint32_t a;
    asm("{ .reg .u64 t; cvta.to.shared.u64 t, %1; cvt.u32.u64 %0, t; }"
        : "=r"(a) : "l"(p));
    return a;
}

__device__ __forceinline__ void ldsm4(uint32_t& r0, uint32_t& r1,
                                      uint32_t& r2, uint32_t& r3, uint32_t addr) {
    asm volatile("ldmatrix.sync.aligned.m8n8.x4.shared.b16 {%0,%1,%2,%3}, [%4];"
        : "=r"(r0), "=r"(r1), "=r"(r2), "=r"(r3) : "r"(addr));
}
__device__ __forceinline__ void ldsm4t(uint32_t& r0, uint32_t& r1,
                                       uint32_t& r2, uint32_t& r3, uint32_t addr) {
    asm volatile("ldmatrix.sync.aligned.m8n8.x4.trans.shared.b16 {%0,%1,%2,%3}, [%4];"
        : "=r"(r0), "=r"(r1), "=r"(r2), "=r"(r3) : "r"(addr));
}

__device__ __forceinline__ void mma16(float* c, uint32_t a0, uint32_t a1,
                                      uint32_t a2, uint32_t a3,
                                      uint32_t b0, uint32_t b1) {
    asm volatile("mma.sync.aligned.m16n8k16.row.col.f32.f16.f16.f32 "
        "{%0,%1,%2,%3}, {%4,%5,%6,%7}, {%8,%9}, {%0,%1,%2,%3};"
        : "+f"(c[0]), "+f"(c[1]), "+f"(c[2]), "+f"(c[3])
        : "r"(a0), "r"(a1), "r"(a2), "r"(a3), "r"(b0), "r"(b1));
}

#define CP16(dst, src) \
    asm volatile("cp.async.cg.shared.global [%0], [%1], 16;" :: "r"(dst), "l"(src))
#define CP16P(dst, src, sz) \
    asm volatile("cp.async.cg.shared.global [%0], [%1], 16, %2;" :: "r"(dst), "l"(src), "r"(sz))
#define CP_COMMIT() asm volatile("cp.async.commit_group;" ::: "memory")
#define CP_WAIT(n)  asm volatile("cp.async.wait_group %0;" :: "n"(n) : "memory")

// ===========================================================================
// prepass
// ===========================================================================
__global__ void f2h_kernel(const float* __restrict__ src,
                           __half* __restrict__ dst, int n) {
    int i = (blockIdx.x * blockDim.x + threadIdx.x) * 8;
    if (i < n) {
        float4 v0 = *(const float4*)(src + i);
        float4 v1 = *(const float4*)(src + i + 4);
        __half2 h[4];
        h[0] = __floats2half2_rn(v0.x, v0.y);
        h[1] = __floats2half2_rn(v0.z, v0.w);
        h[2] = __floats2half2_rn(v1.x, v1.y);
        h[3] = __floats2half2_rn(v1.z, v1.w);
        *(uint4*)(dst + i) = *(uint4*)h;
    }
}

__global__ void pack_bias_kernel(const float* __restrict__ bq,
                                 const float* __restrict__ bv,
                                 float* __restrict__ dst) {
    int i = blockIdx.x * blockDim.x + threadIdx.x;
    if (i < NQKV) {
        float v = 0.f;
        if (i < 1024)       v = bq[i];
        else if (i >= 2048) v = bv[i - 2048];
        dst[i] = v;
    }
}

// ===========================================================================
// GEMM: C[M,N] = A[M,1024] @ W[N,1024]^T + bias (fp16 mma.sync)
// Block 128x128, BK=64 halves, 256 thr = 8 warps (2m x 4n), warp tile 64x32.
// SMEM rows 144B: LDSM conflict-free. 16 K-stages, double-buffered.
// ===========================================================================
#define G_STAGE_B (256*144)             // 36864 bytes
#define GEMM_SMEM (2*G_STAGE_B)         // 73728

template<bool HALF_OUT>
__global__ __launch_bounds__(256, 2) void gemm_tc(
    const __half* __restrict__ A, const __half* __restrict__ W,
    const float* __restrict__ bias, void* __restrict__ Cv, int M, int N)
{
    extern __shared__ __align__(16) char smraw[];
    const uint32_t sb = s2u(smraw);
    const int tid = threadIdx.x;
    const int wid = tid >> 5, lane = tid & 31;
    const int wm = wid >> 2, wn = wid & 3;
    const int g = lane >> 2, q = lane & 3;
    const int m0 = blockIdx.y * 128;
    const int n0 = blockIdx.x * 128;

    const uint32_t lmRow = (uint32_t)(lane & 15) * 144 + (uint32_t)(lane >> 4) * 16;
    uint32_t aBase[4], bBase[2];
    #pragma unroll
    for (int mi = 0; mi < 4; mi++)
        aBase[mi] = (uint32_t)(64*wm + 16*mi) * 144 + lmRow;
    #pragma unroll
    for (int p = 0; p < 2; p++)
        bBase[p] = 128u*144 + (uint32_t)(32*wn + 16*p) * 144 + lmRow;

    float c[4][4][4];
    #pragma unroll
    for (int mi = 0; mi < 4; mi++)
        #pragma unroll
        for (int ni = 0; ni < 4; ni++)
            #pragma unroll
            for (int e = 0; e < 4; e++) c[mi][ni][e] = 0.f;

    auto load_stage = [&](int s) {
        const uint32_t base = sb + (s & 1) * G_STAGE_B;
        const int k0 = s * 64;
        #pragma unroll
        for (int i = 0; i < 4; i++) {
            int idx = tid + 256*i;
            int row = idx >> 3, lc = idx & 7;
            int gm = m0 + row;
            const __half* asrc = A + (size_t)(gm < M ? gm : 0) * NSTATE + k0 + lc*8;
            CP16P(base + row*144 + lc*16, asrc, (gm < M) ? 16 : 0);
            const __half* bsrc = W + (size_t)(n0 + row) * NSTATE + k0 + lc*8;
            CP16(base + 128*144 + row*144 + lc*16, bsrc);
        }
    };

    load_stage(0); CP_COMMIT();
    for (int s = 0; s < 16; s++) {
        if (s + 1 < 16) { load_stage(s + 1); CP_COMMIT(); }
        else            { CP_COMMIT(); }
        CP_WAIT(1);
        __syncthreads();

        const uint32_t stg = sb + (s & 1) * G_STAGE_B;
        #pragma unroll
        for (int kd = 0; kd < 4; kd++) {
            uint32_t a[4][4];
            #pragma unroll
            for (int mi = 0; mi < 4; mi++)
                ldsm4(a[mi][0], a[mi][1], a[mi][2], a[mi][3],
                      stg + aBase[mi] + kd*32);
            #pragma unroll
            for (int p = 0; p < 2; p++) {
                uint32_t t0, t1, t2, t3;
                ldsm4(t0, t1, t2, t3, stg + bBase[p] + kd*32);
                #pragma unroll
                for (int mi = 0; mi < 4; mi++) {
                    mma16(c[mi][2*p],   a[mi][0], a[mi][1], a[mi][2], a[mi][3], t0, t2);
                    mma16(c[mi][2*p+1], a[mi][0], a[mi][1], a[mi][2], a[mi][3], t1, t3);
                }
            }
        }
        __syncthreads();
    }

    // epilogue
    #pragma unroll
    for (int ni = 0; ni < 4; ni++) {
        const int col = n0 + 32*wn + 8*ni + 2*q;
        float bx = 0.f, by = 0.f;
        if (bias) { bx = bias[col]; by = bias[col+1]; }
        #pragma unroll
        for (int mi = 0; mi < 4; mi++) {
            int row_lo = m0 + 64*wm + 16*mi + g;
            float v0 = c[mi][ni][0] + bx, v1 = c[mi][ni][1] + by;
            float v2 = c[mi][ni][2] + bx, v3 = c[mi][ni][3] + by;
            if (HALF_OUT) {
                __half* C = (__half*)Cv;
                if (row_lo < M)
                    *(__half2*)(C + (size_t)row_lo*N + col) = __floats2half2_rn(v0, v1);
                if (row_lo + 8 < M)
                    *(__half2*)(C + (size_t)(row_lo+8)*N + col) = __floats2half2_rn(v2, v3);
            } else {
                float* C = (float*)Cv;
                if (row_lo < M)
                    *(float2*)(C + (size_t)row_lo*N + col) = make_float2(v0, v1);
                if (row_lo + 8 < M)
                    *(float2*)(C + (size_t)(row_lo+8)*N + col) = make_float2(v2, v3);
            }
        }
    }
}

// ===========================================================================
// Flash attention, fp16 mma.sync, double-buffered KV prefetch.
// BQ=128, BKV=64, 256 thr = 8 warps; warp: 16 q-rows x 64 kv-cols.
// Q/K/V read from fused qkv buffer (row stride 3072).
// SMEM halves (rows 72h=144B): Q[128] | K[64]x2 | V[64]x2 | P[128]
// ===========================================================================
#define Q0H   0
#define K0H   9216      // + buf*4608
#define V0H   18432     // + buf*4608
#define P0H   27648
#define ATT_SMEM ((P0H + 9216) * 2)     // 73728 bytes

__global__ __launch_bounds__(256, 2) void attn_tc(
    const __half* __restrict__ QKV, __half* __restrict__ Og)
{
    extern __shared__ __align__(16) char smraw[];
    __half* smh = (__half*)smraw;
    const uint32_t sb = s2u(smraw);
    const int tid  = threadIdx.x;
    const int w    = tid >> 5, lane = tid & 31;
    const int g    = lane >> 2, q = lane & 3;
    const int q0   = blockIdx.x * 128;
    const int h    = blockIdx.y;
    const int b    = blockIdx.z;

    const __half* Qg = QKV;
    const __half* Kg = QKV + 1024;
    const __half* Vg = QKV + 2048;

    const uint32_t Qb = sb + Q0H*2, Pb = sb + P0H*2;
    const uint32_t lmRow = (uint32_t)(lane & 15) * 144 + (uint32_t)(lane >> 4) * 16;

    const uint32_t qA = Qb + (uint32_t)(16*w)*144 + lmRow;
    const uint32_t pA = Pb + (uint32_t)(16*w)*144 + lmRow;

    // load Q tile: 128 rows x 8 chunks, 4/thread
    {
        #pragma unroll
        for (int i = 0; i < 4; i++) {
            int idx = tid + 256*i;
            int row = idx >> 3, lc = idx & 7;
            int s = q0 + row;
            const __half* src = Qg + (size_t)(b*SEQ + (s < SEQ ? s : 0))*NQKV
                                + h*HDIM + lc*8;
            CP16P(Qb + row*144 + lc*16, src, (s < SEQ) ? 16 : 0);
        }
        CP_COMMIT();
    }

    const int NKT = (SEQ + 63) / 64;   // 24
    auto load_kv = [&](int kt) {
        const int buf = kt & 1;
        const uint32_t Kb = sb + (K0H + buf*4608)*2;
        const uint32_t Vb = sb + (V0H + buf*4608)*2;
        #pragma unroll
        for (int i = 0; i < 2; i++) {
            int idx = tid + 256*i;
            int row = idx >> 3, lc = idx & 7;
            int s = kt*64 + row;
            size_t base = (size_t)(b*SEQ + (s < SEQ ? s : 0))*NQKV + h*HDIM + lc*8;
            int ok = (s < SEQ) ? 16 : 0;
            CP16P(Kb + row*144 + lc*16, Kg + base, ok);
            CP16P(Vb + row*144 + lc*16, Vg + base, ok);
        }
    };

    load_kv(0); CP_COMMIT();

    float o[8][4];
    #pragma unroll
    for (int nt = 0; nt < 8; nt++)
        #pragma unroll
        for (int e = 0; e < 4; e++) o[nt][e] = 0.f;
    float m_lo = -1e30f, m_hi = -1e30f, l_lo = 0.f, l_hi = 0.f;

    for (int kt = 0; kt < NKT; kt++) {
        __syncthreads();   // all warps done reading the buffer we're about to fill
        if (kt + 1 < NKT) { load_kv(kt + 1); CP_COMMIT(); }
        else              { CP_COMMIT(); }
        CP_WAIT(1);        // Q + KV(kt) complete
        __syncthreads();

        const int buf = kt & 1;
        const uint32_t Kb = sb + (K0H + buf*4608)*2;
        const uint32_t Vb = sb + (V0H + buf*4608)*2;

        // ---- S = Q K^T ----
        float s[8][4];
        #pragma unroll
        for (int nt = 0; nt < 8; nt++)
            #pragma unroll
            for (int e = 0; e < 4; e++) s[nt][e] = 0.f;

        #pragma unroll
        for (int kd = 0; kd < 4; kd++) {
            uint32_t a0, a1, a2, a3;
            ldsm4(a0, a1, a2, a3, qA + kd*32);
            #pragma unroll
            for (int p = 0; p < 4; p++) {
                uint32_t t0, t1, t2, t3;
                ldsm4(t0, t1, t2, t3, Kb + (uint32_t)(16*p)*144 + lmRow + kd*32);
                mma16(s[2*p],   a0, a1, a2, a3, t0, t2);
                mma16(s[2*p+1], a0, a1, a2, a3, t1, t3);
            }
        }

        // ---- online softmax (rows g, g+8; warp-local) ----
        const int jb = kt*64 + 2*q;
        float mxlo = -1e30f, mxhi = -1e30f;
        #pragma unroll
        for (int nt = 0; nt < 8; nt++) {
            const int j0 = jb + 8*nt;
            s[nt][0] = (j0     < SEQ) ? s[nt][0]*0.125f : -1e30f;
            s[nt][1] = (j0 + 1 < SEQ) ? s[nt][1]*0.125f : -1e30f;
            s[nt][2] = (j0     < SEQ) ? s[nt][2]*0.125f : -1e30f;
            s[nt][3] = (j0 + 1 < SEQ) ? s[nt][3]*0.125f : -1e30f;
            mxlo = fmaxf(mxlo, fmaxf(s[nt][0], s[nt][1]));
            mxhi = fmaxf(mxhi, fmaxf(s[nt][2], s[nt][3]));
        }
        mxlo = fmaxf(mxlo, __shfl_xor_sync(0xffffffffu, mxlo, 1));
        mxlo = fmaxf(mxlo, __shfl_xor_sync(0xffffffffu, mxlo, 2));
        mxhi = fmaxf(mxhi, __shfl_xor_sync(0xffffffffu, mxhi, 1));
        mxhi = fmaxf(mxhi, __shfl_xor_sync(0xffffffffu, mxhi, 2));

        const float mn_lo = fmaxf(m_lo, mxlo);
        const float mn_hi = fmaxf(m_hi, mxhi);
        const float al_lo = __expf(m_lo - mn_lo);
        const float al_hi = __expf(m_hi - mn_hi);
        float sl = 0.f, sh = 0.f;
        #pragma unroll
        for (int nt = 0; nt < 8; nt++) {
            s[nt][0] = __expf(s[nt][0] - mn_lo);
            s[nt][1] = __expf(s[nt][1] - mn_lo);
            s[nt][2] = __expf(s[nt][2] - mn_hi);
            s[nt][3] = __expf(s[nt][3] - mn_hi);
            sl += s[nt][0] + s[nt][1];
            sh += s[nt][2] + s[nt][3];
        }
        sl += __shfl_xor_sync(0xffffffffu, sl, 1);
        sl += __shfl_xor_sync(0xffffffffu, sl, 2);
        sh += __shfl_xor_sync(0xffffffffu, sh, 1);
        sh += __shfl_xor_sync(0xffffffffu, sh, 2);
        l_lo = l_lo * al_lo + sl;  m_lo = mn_lo;
        l_hi = l_hi * al_hi + sh;  m_hi = mn_hi;
        #pragma unroll
        for (int nt = 0; nt < 8; nt++) {
            o[nt][0] *= al_lo; o[nt][1] *= al_lo;
            o[nt][2] *= al_hi; o[nt][3] *= al_hi;
        }

        // store P (fp16), rows 16w+g and 16w+g+8
        {
            __half* Plo = smh + P0H + (16*w + g)     * 72 + 2*q;
            __half* Phi = smh + P0H + (16*w + g + 8) * 72 + 2*q;
            #pragma unroll
            for (int nt = 0; nt < 8; nt++) {
                *(__half2*)(Plo + 8*nt) = __floats2half2_rn(s[nt][0], s[nt][1]);
                *(__half2*)(Phi + 8*nt) = __floats2half2_rn(s[nt][2], s[nt][3]);
            }
        }
        __syncwarp();

        // ---- O += P V ----
        #pragma unroll
        for (int kj = 0; kj < 4; kj++) {
            uint32_t a0, a1, a2, a3;
            ldsm4(a0, a1, a2, a3, pA + kj*32);
            const uint32_t vrow = Vb + (uint32_t)(16*kj)*144 + lmRow;
            #pragma unroll
            for (int dt = 0; dt < 4; dt++) {
                uint32_t t0, t1, t2, t3;
                ldsm4t(t0, t1, t2, t3, vrow + dt*32);
                mma16(o[2*dt],   a0, a1, a2, a3, t0, t1);
                mma16(o[2*dt+1], a0, a1, a2, a3, t2, t3);
            }
        }
        __syncwarp();
    }

    // ---- epilogue ----
    const float il_lo = 1.f / l_lo, il_hi = 1.f / l_hi;
    const int row_lo = q0 + 16*w + g;
    const int row_hi = row_lo + 8;
    #pragma unroll
    for (int nt = 0; nt < 8; nt++) {
        const int d = 8*nt + 2*q;
        if (row_lo < SEQ)
            *(__half2*)(Og + (size_t)(b*SEQ + row_lo)*NSTATE + h*HDIM + d) =
                __floats2half2_rn(o[nt][0]*il_lo, o[nt][1]*il_lo);
        if (row_hi < SEQ)
            *(__half2*)(Og + (size_t)(b*SEQ + row_hi)*NSTATE + h*HDIM + d) =
                __floats2half2_rn(o[nt][2]*il_hi, o[nt][3]*il_hi);
    }
}

// ===========================================================================
extern "C" void kernel_launch(void* const* d_in, const int* in_sizes, int n_in,
                              void* d_out, int out_size)
{
    const float* x  = (const float*)d_in[0];
    const float* Wq = (const float*)d_in[1];
    const float* bq = (const float*)d_in[2];
    const float* Wk = (const float*)d_in[3];
    const float* Wv = (const float*)d_in[4];
    const float* bv = (const float*)d_in[5];
    const float* Wo = (const float*)d_in[6];
    const float* bo = (const float*)d_in[7];
    float* out = (float*)d_out;

    __half *xh, *wqkv, *wo, *qkv, *att;
    float* bqkv;
    cudaGetSymbolAddress((void**)&xh,   g_x);
    cudaGetSymbolAddress((void**)&wqkv, g_wqkv);
    cudaGetSymbolAddress((void**)&wo,   g_wo);
    cudaGetSymbolAddress((void**)&qkv,  g_qkv);
    cudaGetSymbolAddress((void**)&att,  g_att);
    cudaGetSymbolAddress((void**)&bqkv, g_bqkv);

    cudaFuncSetAttribute(gemm_tc<true>,
                         cudaFuncAttributeMaxDynamicSharedMemorySize, GEMM_SMEM);
    cudaFuncSetAttribute(gemm_tc<false>,
                         cudaFuncAttributeMaxDynamicSharedMemorySize, GEMM_SMEM);
    cudaFuncSetAttribute(attn_tc,
                         cudaFuncAttributeMaxDynamicSharedMemorySize, ATT_SMEM);

    const int nx = TOK * NSTATE, nw = NSTATE * NSTATE;
    f2h_kernel<<<nx/2048, 256>>>(x,  xh, nx);
    f2h_kernel<<<nw/2048, 256>>>(Wq, wqkv,        nw);
    f2h_kernel<<<nw/2048, 256>>>(Wk, wqkv + nw,   nw);
    f2h_kernel<<<nw/2048, 256>>>(Wv, wqkv + 2*nw, nw);
    f2h_kernel<<<nw/2048, 256>>>(Wo, wo, nw);
    pack_bias_kernel<<<NQKV/256, 256>>>(bq, bv, bqkv);

    // fused QKV projection: [6000,1024] @ [3072,1024]^T -> [6000,3072]
    gemm_tc<true><<<dim3(NQKV/128, (TOK+127)/128), 256, GEMM_SMEM>>>(
        xh, wqkv, bqkv, qkv, TOK, NQKV);

    attn_tc<<<dim3((SEQ+127)/128, NHEAD, BATCH), 256, ATT_SMEM>>>(qkv, att);

    gemm_tc<false><<<dim3(NSTATE/128, (TOK+127)/128), 256, GEMM_SMEM>>>(
        att, wo, bo, out, TOK, NSTATE);
}

// round 6
// speedup vs baseline: 7.1438x; 1.0612x over previous
#include <cuda_runtime.h>
#include <cuda_fp16.h>
#include <math.h>
#include <stdint.h>

#define BATCH  4
#define SEQ    1500
#define NSTATE 1024
#define NQKV   3072
#define NHEAD  16
#define HDIM   64
#define TOK    (BATCH*SEQ)   // 6000
#define NW     (NSTATE*NSTATE)
#define NX     (TOK*NSTATE)

// Scratch (allocation-free rule: __device__ globals), all fp16
__device__ __half g_x[NX];
__device__ __half g_qkv[TOK*NQKV];          // fused q|k|v, row stride 3072
__device__ __half g_att[NX];
__device__ __half g_wqkv[NQKV*NSTATE];      // Wq rows 0..1023, Wk 1024.., Wv 2048..
__device__ __half g_wo[NW];
__device__ float  g_bqkv[NQKV];

// ===========================================================================
// helpers
// ===========================================================================
__device__ __forceinline__ uint32_t s2u(const void* p) {
    uint32_t a;
    asm("{ .reg .u64 t; cvta.to.shared.u64 t, %1; cvt.u32.u64 %0, t; }"
        : "=r"(a) : "l"(p));
    return a;
}

__device__ __forceinline__ void ldsm4(uint32_t& r0, uint32_t& r1,
                                      uint32_t& r2, uint32_t& r3, uint32_t addr) {
    asm volatile("ldmatrix.sync.aligned.m8n8.x4.shared.b16 {%0,%1,%2,%3}, [%4];"
        : "=r"(r0), "=r"(r1), "=r"(r2), "=r"(r3) : "r"(addr));
}
__device__ __forceinline__ void ldsm4t(uint32_t& r0, uint32_t& r1,
                                       uint32_t& r2, uint32_t& r3, uint32_t addr) {
    asm volatile("ldmatrix.sync.aligned.m8n8.x4.trans.shared.b16 {%0,%1,%2,%3}, [%4];"
        : "=r"(r0), "=r"(r1), "=r"(r2), "=r"(r3) : "r"(addr));
}

__device__ __forceinline__ void mma16(float* c, uint32_t a0, uint32_t a1,
                                      uint32_t a2, uint32_t a3,
                                      uint32_t b0, uint32_t b1) {
    asm volatile("mma.sync.aligned.m16n8k16.row.col.f32.f16.f16.f32 "
        "{%0,%1,%2,%3}, {%4,%5,%6,%7}, {%8,%9}, {%0,%1,%2,%3};"
        : "+f"(c[0]), "+f"(c[1]), "+f"(c[2]), "+f"(c[3])
        : "r"(a0), "r"(a1), "r"(a2), "r"(a3), "r"(b0), "r"(b1));
}

__device__ __forceinline__ uint32_t packh2(float a, float b) {
    __half2 h = __floats2half2_rn(a, b);
    return *(uint32_t*)&h;
}

#define CP16(dst, src) \
    asm volatile("cp.async.cg.shared.global [%0], [%1], 16;" :: "r"(dst), "l"(src))
#define CP16P(dst, src, sz) \
    asm volatile("cp.async.cg.shared.global [%0], [%1], 16, %2;" :: "r"(dst), "l"(src), "r"(sz))
#define CP_COMMIT() asm volatile("cp.async.commit_group;" ::: "memory")
#define CP_WAIT(n)  asm volatile("cp.async.wait_group %0;" :: "n"(n) : "memory")

// ===========================================================================
// single fused prepass: x->g_x, Wq|Wk|Wv->g_wqkv, Wo->g_wo, bias->g_bqkv
// chunk = 8 elements
// ===========================================================================
#define PREP_CHUNKS ((NX + 4*NW + NQKV) / 8)

__global__ void prep_kernel(const float* __restrict__ x,
                            const float* __restrict__ Wq,
                            const float* __restrict__ Wk,
                            const float* __restrict__ Wv,
                            const float* __restrict__ Wo,
                            const float* __restrict__ bq,
                            const float* __restrict__ bv)
{
    int i = (blockIdx.x * blockDim.x + threadIdx.x) * 8;
    const float* src;
    __half* dst;
    if (i < NX) {
        src = x + i; dst = g_x + i;
    } else if (i < NX + 3*NW) {
        int j = i - NX;
        src = (j < NW) ? Wq + j : (j < 2*NW) ? Wk + (j - NW) : Wv + (j - 2*NW);
        dst = g_wqkv + j;
    } else if (i < NX + 4*NW) {
        int j = i - NX - 3*NW;
        src = Wo + j; dst = g_wo + j;
    } else if (i < NX + 4*NW + NQKV) {
        int j = i - NX - 4*NW;
        #pragma unroll
        for (int e = 0; e < 8; e++) {
            int c = j + e;
            float v = 0.f;
            if (c < 1024)       v = bq[c];
            else if (c >= 2048) v = bv[c - 2048];
            g_bqkv[c] = v;
        }
        return;
    } else return;

    float4 v0 = *(const float4*)(src);
    float4 v1 = *(const float4*)(src + 4);
    __half2 h[4];
    h[0] = __floats2half2_rn(v0.x, v0.y);
    h[1] = __floats2half2_rn(v0.z, v0.w);
    h[2] = __floats2half2_rn(v1.x, v1.y);
    h[3] = __floats2half2_rn(v1.z, v1.w);
    *(uint4*)dst = *(uint4*)h;
}

// ===========================================================================
// GEMM: C[M,N] = A[M,1024] @ W[N,1024]^T + bias (fp16 mma.sync)
// Block 128x128, BK=64 halves, 256 thr = 8 warps (2m x 4n), warp tile 64x32.
// SMEM rows 144B: LDSM conflict-free. 16 K-stages, double-buffered.
// ===========================================================================
#define G_STAGE_B (256*144)             // 36864 bytes
#define GEMM_SMEM (2*G_STAGE_B)         // 73728

template<bool HALF_OUT>
__global__ __launch_bounds__(256, 2) void gemm_tc(
    const __half* __restrict__ A, const __half* __restrict__ W,
    const float* __restrict__ bias, void* __restrict__ Cv, int M, int N)
{
    extern __shared__ __align__(16) char smraw[];
    const uint32_t sb = s2u(smraw);
    const int tid = threadIdx.x;
    const int wid = tid >> 5, lane = tid & 31;
    const int wm = wid >> 2, wn = wid & 3;
    const int g = lane >> 2, q = lane & 3;
    const int m0 = blockIdx.y * 128;
    const int n0 = blockIdx.x * 128;

    const uint32_t lmRow = (uint32_t)(lane & 15) * 144 + (uint32_t)(lane >> 4) * 16;
    uint32_t aBase[4], bBase[2];
    #pragma unroll
    for (int mi = 0; mi < 4; mi++)
        aBase[mi] = (uint32_t)(64*wm + 16*mi) * 144 + lmRow;
    #pragma unroll
    for (int p = 0; p < 2; p++)
        bBase[p] = 128u*144 + (uint32_t)(32*wn + 16*p) * 144 + lmRow;

    float c[4][4][4];
    #pragma unroll
    for (int mi = 0; mi < 4; mi++)
        #pragma unroll
        for (int ni = 0; ni < 4; ni++)
            #pragma unroll
            for (int e = 0; e < 4; e++) c[mi][ni][e] = 0.f;

    auto load_stage = [&](int s) {
        const uint32_t base = sb + (s & 1) * G_STAGE_B;
        const int k0 = s * 64;
        #pragma unroll
        for (int i = 0; i < 4; i++) {
            int idx = tid + 256*i;
            int row = idx >> 3, lc = idx & 7;
            int gm = m0 + row;
            const __half* asrc = A + (size_t)(gm < M ? gm : 0) * NSTATE + k0 + lc*8;
            CP16P(base + row*144 + lc*16, asrc, (gm < M) ? 16 : 0);
            const __half* bsrc = W + (size_t)(n0 + row) * NSTATE + k0 + lc*8;
            CP16(base + 128*144 + row*144 + lc*16, bsrc);
        }
    };

    load_stage(0); CP_COMMIT();
    for (int s = 0; s < 16; s++) {
        if (s + 1 < 16) { load_stage(s + 1); CP_COMMIT(); }
        else            { CP_COMMIT(); }
        CP_WAIT(1);
        __syncthreads();

        const uint32_t stg = sb + (s & 1) * G_STAGE_B;
        #pragma unroll
        for (int kd = 0; kd < 4; kd++) {
            uint32_t a[4][4];
            #pragma unroll
            for (int mi = 0; mi < 4; mi++)
                ldsm4(a[mi][0], a[mi][1], a[mi][2], a[mi][3],
                      stg + aBase[mi] + kd*32);
            #pragma unroll
            for (int p = 0; p < 2; p++) {
                uint32_t t0, t1, t2, t3;
                ldsm4(t0, t1, t2, t3, stg + bBase[p] + kd*32);
                #pragma unroll
                for (int mi = 0; mi < 4; mi++) {
                    mma16(c[mi][2*p],   a[mi][0], a[mi][1], a[mi][2], a[mi][3], t0, t2);
                    mma16(c[mi][2*p+1], a[mi][0], a[mi][1], a[mi][2], a[mi][3], t1, t3);
                }
            }
        }
        __syncthreads();
    }

    // epilogue
    #pragma unroll
    for (int ni = 0; ni < 4; ni++) {
        const int col = n0 + 32*wn + 8*ni + 2*q;
        float bx = 0.f, by = 0.f;
        if (bias) { bx = bias[col]; by = bias[col+1]; }
        #pragma unroll
        for (int mi = 0; mi < 4; mi++) {
            int row_lo = m0 + 64*wm + 16*mi + g;
            float v0 = c[mi][ni][0] + bx, v1 = c[mi][ni][1] + by;
            float v2 = c[mi][ni][2] + bx, v3 = c[mi][ni][3] + by;
            if (HALF_OUT) {
                __half* C = (__half*)Cv;
                if (row_lo < M)
                    *(__half2*)(C + (size_t)row_lo*N + col) = __floats2half2_rn(v0, v1);
                if (row_lo + 8 < M)
                    *(__half2*)(C + (size_t)(row_lo+8)*N + col) = __floats2half2_rn(v2, v3);
            } else {
                float* C = (float*)Cv;
                if (row_lo < M)
                    *(float2*)(C + (size_t)row_lo*N + col) = make_float2(v0, v1);
                if (row_lo + 8 < M)
                    *(float2*)(C + (size_t)(row_lo+8)*N + col) = make_float2(v2, v3);
            }
        }
    }
}

// ===========================================================================
// Flash attention, fp16 mma.sync, double-buffered KV prefetch,
// register-resident P (S C-frag == PV A-frag layout; no P SMEM round-trip).
// BQ=128, BKV=64, 256 thr = 8 warps; warp: 16 q-rows x 64 kv-cols.
// SMEM halves (rows 72h=144B): Q[128] | K[64]x2 | V[64]x2  = 55296 B
// ===========================================================================
#define Q0H   0
#define K0H   9216      // + buf*4608
#define V0H   18432     // + buf*4608
#define ATT_SMEM ((V0H + 2*4608) * 2)   // 55296 bytes

__global__ __launch_bounds__(256, 2) void attn_tc(
    const __half* __restrict__ QKV, __half* __restrict__ Og)
{
    extern __shared__ __align__(16) char smraw[];
    const uint32_t sb = s2u(smraw);
    const int tid  = threadIdx.x;
    const int w    = tid >> 5, lane = tid & 31;
    const int g    = lane >> 2, q = lane & 3;
    const int q0   = blockIdx.x * 128;
    const int h    = blockIdx.y;
    const int b    = blockIdx.z;

    const __half* Qg = QKV;
    const __half* Kg = QKV + 1024;
    const __half* Vg = QKV + 2048;

    const uint32_t Qb = sb + Q0H*2;
    const uint32_t lmRow = (uint32_t)(lane & 15) * 144 + (uint32_t)(lane >> 4) * 16;
    const uint32_t qA = Qb + (uint32_t)(16*w)*144 + lmRow;

    // load Q tile: 128 rows x 8 chunks, 4/thread
    {
        #pragma unroll
        for (int i = 0; i < 4; i++) {
            int idx = tid + 256*i;
            int row = idx >> 3, lc = idx & 7;
            int s = q0 + row;
            const __half* src = Qg + (size_t)(b*SEQ + (s < SEQ ? s : 0))*NQKV
                                + h*HDIM + lc*8;
            CP16P(Qb + row*144 + lc*16, src, (s < SEQ) ? 16 : 0);
        }
        CP_COMMIT();
    }

    const int NKT = (SEQ + 63) / 64;   // 24
    auto load_kv = [&](int kt) {
        const int buf = kt & 1;
        const uint32_t Kb = sb + (K0H + buf*4608)*2;
        const uint32_t Vb = sb + (V0H + buf*4608)*2;
        #pragma unroll
        for (int i = 0; i < 2; i++) {
            int idx = tid + 256*i;
            int row = idx >> 3, lc = idx & 7;
            int s = kt*64 + row;
            size_t base = (size_t)(b*SEQ + (s < SEQ ? s : 0))*NQKV + h*HDIM + lc*8;
            int ok = (s < SEQ) ? 16 : 0;
            CP16P(Kb + row*144 + lc*16, Kg + base, ok);
            CP16P(Vb + row*144 + lc*16, Vg + base, ok);
        }
    };

    load_kv(0); CP_COMMIT();

    float o[8][4];
    #pragma unroll
    for (int nt = 0; nt < 8; nt++)
        #pragma unroll
        for (int e = 0; e < 4; e++) o[nt][e] = 0.f;
    float m_lo = -1e30f, m_hi = -1e30f, l_lo = 0.f, l_hi = 0.f;

    for (int kt = 0; kt < NKT; kt++) {
        __syncthreads();   // all warps done reading the buffer we're about to fill
        if (kt + 1 < NKT) { load_kv(kt + 1); CP_COMMIT(); }
        else              { CP_COMMIT(); }
        CP_WAIT(1);        // Q + KV(kt) complete
        __syncthreads();

        const int buf = kt & 1;
        const uint32_t Kb = sb + (K0H + buf*4608)*2;
        const uint32_t Vb = sb + (V0H + buf*4608)*2;

        // ---- S = Q K^T ----
        float s[8][4];
        #pragma unroll
        for (int nt = 0; nt < 8; nt++)
            #pragma unroll
            for (int e = 0; e < 4; e++) s[nt][e] = 0.f;

        #pragma unroll
        for (int kd = 0; kd < 4; kd++) {
            uint32_t a0, a1, a2, a3;
            ldsm4(a0, a1, a2, a3, qA + kd*32);
            #pragma unroll
            for (int p = 0; p < 4; p++) {
                uint32_t t0, t1, t2, t3;
                ldsm4(t0, t1, t2, t3, Kb + (uint32_t)(16*p)*144 + lmRow + kd*32);
                mma16(s[2*p],   a0, a1, a2, a3, t0, t2);
                mma16(s[2*p+1], a0, a1, a2, a3, t1, t3);
            }
        }

        // ---- online softmax (rows g, g+8; warp-local) ----
        const int jb = kt*64 + 2*q;
        float mxlo = -1e30f, mxhi = -1e30f;
        #pragma unroll
        for (int nt = 0; nt < 8; nt++) {
            const int j0 = jb + 8*nt;
            s[nt][0] = (j0     < SEQ) ? s[nt][0]*0.125f : -1e30f;
            s[nt][1] = (j0 + 1 < SEQ) ? s[nt][1]*0.125f : -1e30f;
            s[nt][2] = (j0     < SEQ) ? s[nt][2]*0.125f : -1e30f;
            s[nt][3] = (j0 + 1 < SEQ) ? s[nt][3]*0.125f : -1e30f;
            mxlo = fmaxf(mxlo, fmaxf(s[nt][0], s[nt][1]));
            mxhi = fmaxf(mxhi, fmaxf(s[nt][2], s[nt][3]));
        }
        mxlo = fmaxf(mxlo, __shfl_xor_sync(0xffffffffu, mxlo, 1));
        mxlo = fmaxf(mxlo, __shfl_xor_sync(0xffffffffu, mxlo, 2));
        mxhi = fmaxf(mxhi, __shfl_xor_sync(0xffffffffu, mxhi, 1));
        mxhi = fmaxf(mxhi, __shfl_xor_sync(0xffffffffu, mxhi, 2));

        const float mn_lo = fmaxf(m_lo, mxlo);
        const float mn_hi = fmaxf(m_hi, mxhi);
        const float al_lo = __expf(m_lo - mn_lo);
        const float al_hi = __expf(m_hi - mn_hi);
        float sl = 0.f, sh = 0.f;
        #pragma unroll
        for (int nt = 0; nt < 8; nt++) {
            s[nt][0] = __expf(s[nt][0] - mn_lo);
            s[nt][1] = __expf(s[nt][1] - mn_lo);
            s[nt][2] = __expf(s[nt][2] - mn_hi);
            s[nt][3] = __expf(s[nt][3] - mn_hi);
            sl += s[nt][0] + s[nt][1];
            sh += s[nt][2] + s[nt][3];
        }
        sl += __shfl_xor_sync(0xffffffffu, sl, 1);
        sl += __shfl_xor_sync(0xffffffffu, sl, 2);
        sh += __shfl_xor_sync(0xffffffffu, sh, 1);
        sh += __shfl_xor_sync(0xffffffffu, sh, 2);
        l_lo = l_lo * al_lo + sl;  m_lo = mn_lo;
        l_hi = l_hi * al_hi + sh;  m_hi = mn_hi;
        #pragma unroll
        for (int nt = 0; nt < 8; nt++) {
            o[nt][0] *= al_lo; o[nt][1] *= al_lo;
            o[nt][2] *= al_hi; o[nt][3] *= al_hi;
        }

        // ---- O += P V : P fragments formed directly from S accumulators ----
        #pragma unroll
        for (int kj = 0; kj < 4; kj++) {
            const uint32_t a0 = packh2(s[2*kj][0],   s[2*kj][1]);
            const uint32_t a1 = packh2(s[2*kj][2],   s[2*kj][3]);
            const uint32_t a2 = packh2(s[2*kj+1][0], s[2*kj+1][1]);
            const uint32_t a3 = packh2(s[2*kj+1][2], s[2*kj+1][3]);
            const uint32_t vrow = Vb + (uint32_t)(16*kj)*144 + lmRow;
            #pragma unroll
            for (int dt = 0; dt < 4; dt++) {
                uint32_t t0, t1, t2, t3;
                ldsm4t(t0, t1, t2, t3, vrow + dt*32);
                mma16(o[2*dt],   a0, a1, a2, a3, t0, t1);
                mma16(o[2*dt+1], a0, a1, a2, a3, t2, t3);
            }
        }
    }

    // ---- epilogue ----
    const float il_lo = 1.f / l_lo, il_hi = 1.f / l_hi;
    const int row_lo = q0 + 16*w + g;
    const int row_hi = row_lo + 8;
    #pragma unroll
    for (int nt = 0; nt < 8; nt++) {
        const int d = 8*nt + 2*q;
        if (row_lo < SEQ)
            *(__half2*)(Og + (size_t)(b*SEQ + row_lo)*NSTATE + h*HDIM + d) =
                __floats2half2_rn(o[nt][0]*il_lo, o[nt][1]*il_lo);
        if (row_hi < SEQ)
            *(__half2*)(Og + (size_t)(b*SEQ + row_hi)*NSTATE + h*HDIM + d) =
                __floats2half2_rn(o[nt][2]*il_hi, o[nt][3]*il_hi);
    }
}

// ===========================================================================
extern "C" void kernel_launch(void* const* d_in, const int* in_sizes, int n_in,
                              void* d_out, int out_size)
{
    const float* x  = (const float*)d_in[0];
    const float* Wq = (const float*)d_in[1];
    const float* bq = (const float*)d_in[2];
    const float* Wk = (const float*)d_in[3];
    const float* Wv = (const float*)d_in[4];
    const float* bv = (const float*)d_in[5];
    const float* Wo = (const float*)d_in[6];
    const float* bo = (const float*)d_in[7];
    float* out = (float*)d_out;

    __half *xh, *wqkv, *wo, *qkv, *att;
    float* bqkv;
    cudaGetSymbolAddress((void**)&xh,   g_x);
    cudaGetSymbolAddress((void**)&wqkv, g_wqkv);
    cudaGetSymbolAddress((void**)&wo,   g_wo);
    cudaGetSymbolAddress((void**)&qkv,  g_qkv);
    cudaGetSymbolAddress((void**)&att,  g_att);
    cudaGetSymbolAddress((void**)&bqkv, g_bqkv);

    cudaFuncSetAttribute(gemm_tc<true>,
                         cudaFuncAttributeMaxDynamicSharedMemorySize, GEMM_SMEM);
    cudaFuncSetAttribute(gemm_tc<false>,
                         cudaFuncAttributeMaxDynamicSharedMemorySize, GEMM_SMEM);
    cudaFuncSetAttribute(attn_tc,
                         cudaFuncAttributeMaxDynamicSharedMemorySize, ATT_SMEM);

    prep_kernel<<<(PREP_CHUNKS + 255)/256, 256>>>(x, Wq, Wk, Wv, Wo, bq, bv);

    // fused QKV projection: [6000,1024] @ [3072,1024]^T -> [6000,3072]
    gemm_tc<true><<<dim3(NQKV/128, (TOK+127)/128), 256, GEMM_SMEM>>>(
        xh, wqkv, bqkv, qkv, TOK, NQKV);

    attn_tc<<<dim3((SEQ+127)/128, NHEAD, BATCH), 256, ATT_SMEM>>>(qkv, att);

    gemm_tc<false><<<dim3(NSTATE/128, (TOK+127)/128), 256, GEMM_SMEM>>>(
        att, wo, bo, out, TOK, NSTATE);
}